// round 14
// baseline (speedup 1.0000x reference)
#include <cuda_runtime.h>
#include <math.h>

// BiTemperedLogisticLoss, T1=0.2, T2=1.2, label_smoothing=0.05.
// exp_t(x,1.2) = (1-0.2x)^-5. b_j = u + 0.2*(mu-a_j), p = b^-5,
// p^0.8 = b^-4, p^1.8 = b^-9.
// Two passes per row (R7 math):
//   pass A (u=1): S5,S6 -> Pade init u1 = (S5/S6)*(S5^{1/5}-1) + 1.
//   pass B (u1):  S4,S5,S6,S9,S10,S11; Newton d = ln(S5)*S5/(5*S6) applied
//     analytically: acc4 = S4-4dS5+10d^2S6, acc9 = S9-9dS10+45d^2S11;
//     hot-index term at u1+d.
// One-hot targets: ah = sum(t*a) = a_hot; rest folds to host constants.
// NEW (R14): gmem -> smem via cp.async.bulk (TMA engine, bypasses the
// per-warp LDG/L1tex path that plateaued at ~4.4TB/s in R7-R13).
// Persistent 148 CTAs, 3-stage 64KB-tile pipeline (depth-2 prefetch),
// mbarrier expect_tx completion, 8 rows/tile, one warp per row from smem.
// Single launch: device scratch + last-CTA finalize (acq_rel, no fences).

#define C_CLASSES 1000
#define C4 250
#define CTA_THREADS 256
#define TILE_ROWS 8
#define ROW_BYTES 4000                 // 1000 floats
#define HALF_TILE (TILE_ROWS * ROW_BYTES)      // 32000 (logits)
#define TILE_BYTES (2 * HALF_TILE)             // 64000 (logits+targets)
#define STAGES 3
#define GRID_CTAS 148

typedef unsigned long long u64;

__device__ float    g_acc   = 0.0f;
__device__ unsigned g_count = 0u;

__device__ __forceinline__ float frcp(float x) {
    float r; asm("rcp.approx.ftz.f32 %0, %1;" : "=f"(r) : "f"(x)); return r;
}
__device__ __forceinline__ float flg2(float x) {
    float r; asm("lg2.approx.ftz.f32 %0, %1;" : "=f"(r) : "f"(x)); return r;
}
__device__ __forceinline__ float fex2(float x) {
    float r; asm("ex2.approx.ftz.f32 %0, %1;" : "=f"(r) : "f"(x)); return r;
}
__device__ __forceinline__ u64 pk2(float lo, float hi) {
    u64 r; asm("mov.b64 %0, {%1, %2};" : "=l"(r) : "f"(lo), "f"(hi)); return r;
}
__device__ __forceinline__ void upk(u64 v, float& lo, float& hi) {
    asm("mov.b64 {%0, %1}, %2;" : "=f"(lo), "=f"(hi) : "l"(v));
}
__device__ __forceinline__ u64 add2(u64 a, u64 b) {
    u64 r; asm("add.rn.f32x2 %0, %1, %2;" : "=l"(r) : "l"(a), "l"(b)); return r;
}
__device__ __forceinline__ u64 mul2(u64 a, u64 b) {
    u64 r; asm("mul.rn.f32x2 %0, %1, %2;" : "=l"(r) : "l"(a), "l"(b)); return r;
}
__device__ __forceinline__ u64 fma2(u64 a, u64 b, u64 c) {
    u64 r; asm("fma.rn.f32x2 %0, %1, %2, %3;" : "=l"(r) : "l"(a), "l"(b), "l"(c)); return r;
}
__device__ __forceinline__ u64 warp_sum2(u64 v) {
#pragma unroll
    for (int o = 16; o; o >>= 1)
        v = add2(v, __shfl_xor_sync(0xffffffffu, v, o));
    return v;
}
__device__ __forceinline__ float warp_sum(float v) {
#pragma unroll
    for (int o = 16; o; o >>= 1) v += __shfl_xor_sync(0xffffffffu, v, o);
    return v;
}
__device__ __forceinline__ float warp_max(float v) {
#pragma unroll
    for (int o = 16; o; o >>= 1) v = fmaxf(v, __shfl_xor_sync(0xffffffffu, v, o));
    return v;
}

__device__ __forceinline__ void mbar_init(unsigned addr, unsigned count) {
    asm volatile("mbarrier.init.shared.b64 [%0], %1;" :: "r"(addr), "r"(count) : "memory");
}
__device__ __forceinline__ void mbar_expect_tx(unsigned addr, unsigned bytes) {
    asm volatile("mbarrier.arrive.expect_tx.shared.b64 _, [%0], %1;"
                 :: "r"(addr), "r"(bytes) : "memory");
}
__device__ __forceinline__ void mbar_wait(unsigned addr, unsigned parity) {
    asm volatile(
        "{\n\t.reg .pred P;\n\t"
        "WL_%=:\n\t"
        "mbarrier.try_wait.parity.acquire.cta.shared::cta.b64 P, [%0], %1, 0x989680;\n\t"
        "@P bra.uni WD_%=;\n\t"
        "bra.uni WL_%=;\n\t"
        "WD_%=:\n\t}"
        :: "r"(addr), "r"(parity) : "memory");
}
__device__ __forceinline__ void bulk_cp(unsigned sdst, const void* gsrc,
                                        unsigned bytes, unsigned mbar) {
    asm volatile("cp.async.bulk.shared::cta.global.mbarrier::complete_tx::bytes "
                 "[%0], [%1], %2, [%3];"
                 :: "r"(sdst), "l"(gsrc), "r"(bytes), "r"(mbar) : "memory");
}

__global__ __launch_bounds__(CTA_THREADS, 1)
void btll_kernel(const float* __restrict__ inp, const float* __restrict__ tgt,
                 float* __restrict__ out, int N,
                 float ksum, float t_off, float t_delta, float inv_n) {
    extern __shared__ unsigned char sm[];
    __shared__ u64 mbar_store[STAGES];
    __shared__ float blk_acc;

    const int tid  = threadIdx.x;
    const int warp = tid >> 5;
    const int lane = tid & 31;
    const int ntiles = (N + TILE_ROWS - 1) / TILE_ROWS;

    const unsigned sbase = (unsigned)__cvta_generic_to_shared(sm);
    const unsigned mb0   = (unsigned)__cvta_generic_to_shared(mbar_store);

    if (tid == 0) {
        blk_acc = 0.0f;
#pragma unroll
        for (int s = 0; s < STAGES; s++) mbar_init(mb0 + 8 * s, 1);
        // fence so TMA (async proxy) sees the initialized barriers
        asm volatile("fence.proxy.async.shared::cta;" ::: "memory");
    }
    __syncthreads();

    // Producer helper: issue one tile's 16 bulk copies into a stage.
    auto issue = [&](int it) {
        int tile = blockIdx.x + it * GRID_CTAS;
        if (tile >= ntiles) return;
        int stage = it % STAGES;
        unsigned mb = mb0 + 8 * stage;
        unsigned dst = sbase + stage * TILE_BYTES;
        int rows = min(TILE_ROWS, N - tile * TILE_ROWS);
        mbar_expect_tx(mb, (unsigned)(rows * 2 * ROW_BYTES));
#pragma unroll
        for (int r = 0; r < TILE_ROWS; r++) {
            if (r < rows) {
                size_t row = (size_t)tile * TILE_ROWS + r;
                bulk_cp(dst + r * ROW_BYTES, inp + row * C_CLASSES, ROW_BYTES, mb);
                bulk_cp(dst + HALF_TILE + r * ROW_BYTES, tgt + row * C_CLASSES, ROW_BYTES, mb);
            }
        }
    };

    // Prologue: prefetch iterations 0 and 1.
    if (tid == 0) { issue(0); issue(1); }

    float wacc = 0.0f;
    const int myiters = (ntiles - blockIdx.x + GRID_CTAS - 1) / GRID_CTAS;

    for (int it = 0; it < myiters; ++it) {
        if (tid == 0) issue(it + 2);

        const int stage = it % STAGES;
        mbar_wait(mb0 + 8 * stage, (unsigned)((it / STAGES) & 1));

        const int tile = blockIdx.x + it * GRID_CTAS;
        const int row  = tile * TILE_ROWS + warp;
        if (row < N) {
            const float4* sl = (const float4*)(sm + stage * TILE_BYTES + warp * ROW_BYTES);
            const float4* st = (const float4*)(sm + stage * TILE_BYTES + HALF_TILE + warp * ROW_BYTES);

            // Row from smem: logits, max, hot-dot.
            float4 va[8];
            float mx = -3.0e38f, th = 0.0f;
#pragma unroll
            for (int k = 0; k < 8; k++) {
                int c = k * 32 + lane;
                va[k] = (c < C4) ? sl[c]
                                 : make_float4(-3.0e38f, -3.0e38f, -3.0e38f, -3.0e38f);
            }
#pragma unroll
            for (int k = 0; k < 8; k++)
                mx = fmaxf(mx, fmaxf(fmaxf(va[k].x, va[k].y), fmaxf(va[k].z, va[k].w)));
#pragma unroll
            for (int k = 0; k < 8; k++) {
                int c = k * 32 + lane;
                if (c < C4) {
                    float4 t = st[c];
                    th = fmaf(va[k].x, t.x, fmaf(va[k].y, t.y,
                         fmaf(va[k].z, t.z, fmaf(va[k].w, t.w, th))));
                }
            }
            mx = warp_max(mx);
            float ah = warp_sum(th);

            const float mxs = 0.2f * mx;
            u64 E[16];
#pragma unroll
            for (int k = 0; k < 8; k++) {
                int c = k * 32 + lane;
                if (c < C4) {
                    E[2*k]   = pk2(fmaf(-0.2f, va[k].x, mxs), fmaf(-0.2f, va[k].y, mxs));
                    E[2*k+1] = pk2(fmaf(-0.2f, va[k].z, mxs), fmaf(-0.2f, va[k].w, mxs));
                } else {
                    E[2*k]   = pk2(1e15f, 1e15f);
                    E[2*k+1] = pk2(1e15f, 1e15f);
                }
            }

            // Pass A (u=1): Pade init.
            float u;
            {
                const u64 one2 = pk2(1.0f, 1.0f);
                u64 s5 = 0ull, s6 = 0ull;
#pragma unroll
                for (int p = 0; p < 16; p++) {
                    u64 b = add2(one2, E[p]);
                    float bl, bh; upk(b, bl, bh);
                    float rp = frcp(bl * bh);
                    u64 r  = mul2(pk2(rp, rp), pk2(bh, bl));
                    u64 r2 = mul2(r, r);
                    u64 r4 = mul2(r2, r2);
                    s5 = fma2(r4, r, s5);
                    s6 = fma2(r4, r2, s6);
                }
                float x, y, x2, y2;
                upk(s5, x, y); upk(s6, x2, y2);
                u64 both = warp_sum2(pk2(x + y, x2 + y2));
                float S5, S6; upk(both, S5, S6);
                u = fmaf(S5 * frcp(S6), fex2(0.2f * flg2(S5)) - 1.0f, 1.0f);
            }

            // Pass B (u1): all sums; analytic Newton correction.
            const u64 u2p = pk2(u, u);
            u64 s4 = 0ull, s5 = 0ull, s6 = 0ull, s9 = 0ull, s10 = 0ull, s11 = 0ull;
#pragma unroll
            for (int p = 0; p < 16; p++) {
                u64 b = add2(u2p, E[p]);
                float bl, bh; upk(b, bl, bh);
                float rp = frcp(bl * bh);
                u64 r  = mul2(pk2(rp, rp), pk2(bh, bl));
                u64 r2 = mul2(r, r);
                u64 r4 = mul2(r2, r2);
                u64 r8 = mul2(r4, r4);
                u64 r3 = mul2(r2, r);
                s4  = add2(s4, r4);
                s5  = fma2(r4, r,  s5);
                s6  = fma2(r4, r2, s6);
                s9  = fma2(r8, r,  s9);
                s10 = fma2(r8, r2, s10);
                s11 = fma2(r8, r3, s11);
            }
            float x, y, x2, y2;
            upk(s4,  x, y); upk(s9,  x2, y2);
            u64 p49  = warp_sum2(pk2(x + y, x2 + y2));
            upk(s5,  x, y); upk(s10, x2, y2);
            u64 p510 = warp_sum2(pk2(x + y, x2 + y2));
            upk(s6,  x, y); upk(s11, x2, y2);
            u64 p611 = warp_sum2(pk2(x + y, x2 + y2));
            float S4, S9, S5, S10, S6, S11;
            upk(p49, S4, S9); upk(p510, S5, S10); upk(p611, S6, S11);

            float d  = flg2(S5) * 0.13862943611198906f * (S5 * frcp(S6));
            float dd = d * d;
            float acc4 = fmaf(10.0f * dd, S6,  fmaf(-4.0f * d, S5,  S4));
            float acc9 = fmaf(45.0f * dd, S11, fmaf(-9.0f * d, S10, S9));

            float rh  = frcp(fmaf(-0.2f, ah, (u + d) + mxs));
            float rh2 = rh * rh;
            float r4hot = rh2 * rh2;

            if (lane == 0) {
                wacc += ksum
                      - 1.25f * (t_off * (acc4 - (float)C_CLASSES)
                                 + t_delta * (r4hot - 1.0f))
                      + acc9 * (1.0f / 1.8f);
            }
        }
        __syncthreads();   // buffer reuse safety (stage freed for it+3's issue)
    }

    if (lane == 0 && wacc != 0.0f) atomicAdd(&blk_acc, wacc);
    __syncthreads();

    if (tid == 0) {
        atomicAdd(&g_acc, blk_acc);
        unsigned old;
        asm volatile("atom.add.acq_rel.gpu.global.u32 %0, [%1], 1;"
                     : "=r"(old) : "l"(&g_count) : "memory");
        if (old == gridDim.x - 1u) {
            float total = atomicExch(&g_acc, 0.0f);
            atomicExch(&g_count, 0u);
            out[0] = total * inv_n;
        }
    }
}

extern "C" void kernel_launch(void* const* d_in, const int* in_sizes, int n_in,
                              void* d_out, int out_size) {
    const float* inp = (const float*)d_in[0];
    const float* tgt = (const float*)d_in[1];
    float* out = (float*)d_out;

    const int Ctot = in_sizes[0];
    const int N = Ctot / C_CLASSES;

    // Host-side constants (double precision).
    const double ls  = 0.05;
    const double off = ls / (C_CLASSES - 1);
    const double on  = (1.0 - (double)C_CLASSES / (C_CLASSES - 1) * ls) + off; // 0.95
    const double logt_on  = (pow(on  + 1e-8, 0.8) - 1.0) / 0.8;
    const double logt_off = (pow(off + 1e-8, 0.8) - 1.0) / 0.8;
    const double K_on  = on  * logt_on  - pow(on,  1.8) / 1.8;
    const double K_off = off * logt_off - pow(off, 1.8) / 1.8;
    const double ksum  = K_on + (C_CLASSES - 1) * K_off;

    static bool attr_set = false;
    if (!attr_set) {
        cudaFuncSetAttribute(btll_kernel,
                             cudaFuncAttributeMaxDynamicSharedMemorySize,
                             STAGES * TILE_BYTES);
        attr_set = true;
    }

    btll_kernel<<<GRID_CTAS, CTA_THREADS, STAGES * TILE_BYTES>>>(
        inp, tgt, out, N,
        (float)ksum, (float)off, (float)(on - off), (float)(1.0 / N));
}